// round 1
// baseline (speedup 1.0000x reference)
#include <cuda_runtime.h>
#include <math.h>

#define NT 32768   // tokens = 8*4096
#define DD 512
#define HH 1536
#define NE 8

#define BM 64
#define BN 64
#define BK 16

// ---- device scratch (static: no runtime allocation allowed) ----
__device__ int   g_counts[NE];
__device__ int   g_slot[NE * NT];       // slot = token*2 + k
__device__ float g_rw[NE * NT];         // routing weight
__device__ float g_hbuf[(size_t)NT * 2 * HH];   // per-(token,k) hidden acts
__device__ float g_ybuf[(size_t)NT * 2 * DD];   // per-(token,k) weighted outputs

// ---- packed fp32x2 helpers (Blackwell FFMA2: 2x FMA throughput) ----
__device__ __forceinline__ float2 unpack2(unsigned long long v) {
    float2 r;
    asm("mov.b64 {%0, %1}, %2;" : "=f"(r.x), "=f"(r.y) : "l"(v));
    return r;
}
__device__ __forceinline__ void fma2(unsigned long long& d,
                                     unsigned long long a,
                                     unsigned long long b) {
    asm("fma.rn.f32x2 %0, %1, %2, %0;" : "+l"(d) : "l"(a), "l"(b));
}

// ============================================================
// 0) zero expert counters
// ============================================================
__global__ void zero_counts_k() {
    if (threadIdx.x < NE) g_counts[threadIdx.x] = 0;
}

// ============================================================
// 1) gating: logits -> top2 -> softmax -> scatter into buckets
// ============================================================
__global__ void gate_k(const float* __restrict__ x, const float* __restrict__ gw) {
    __shared__ float sgw[NE * DD];
    for (int i = threadIdx.x; i < NE * DD; i += blockDim.x) sgw[i] = gw[i];
    __syncthreads();

    int warp = threadIdx.x >> 5, lane = threadIdx.x & 31;
    int n = blockIdx.x * (blockDim.x >> 5) + warp;
    if (n >= NT) return;
    const float* xr = x + (size_t)n * DD;

    float acc[NE];
#pragma unroll
    for (int e = 0; e < NE; e++) acc[e] = 0.f;
    for (int d = lane; d < DD; d += 32) {
        float xv = xr[d];
#pragma unroll
        for (int e = 0; e < NE; e++) acc[e] += xv * sgw[e * DD + d];
    }
#pragma unroll
    for (int e = 0; e < NE; e++) {
#pragma unroll
        for (int off = 16; off > 0; off >>= 1)
            acc[e] += __shfl_down_sync(0xffffffffu, acc[e], off);
    }
    if (lane == 0) {
        float b0 = -INFINITY, b1 = -INFINITY;
        int i0 = 0, i1 = 0;
#pragma unroll
        for (int e = 0; e < NE; e++) {
            float v = acc[e];
            if (v > b0) { b1 = b0; i1 = i0; b0 = v; i0 = e; }
            else if (v > b1) { b1 = v; i1 = e; }
        }
        float ex = expf(b1 - b0);        // <= 1
        float inv = 1.f / (1.f + ex);
        float w0 = inv;
        float w1 = ex * inv;
        int p0 = atomicAdd(&g_counts[i0], 1);
        g_slot[i0 * NT + p0] = n * 2 + 0;
        g_rw[i0 * NT + p0]   = w0;
        int p1 = atomicAdd(&g_counts[i1], 1);
        g_slot[i1 * NT + p1] = n * 2 + 1;
        g_rw[i1 * NT + p1]   = w1;
    }
}

// ============================================================
// 2) grouped GEMM #1:  h = silu(X @ w1^T) * (X @ w3^T)  per expert
//    A-tile stored DUPLICATED in smem so FFMA2 operands need no packing.
// ============================================================
__global__ __launch_bounds__(256) void ffn1_k(const float* __restrict__ x,
                                              const float* __restrict__ w1,
                                              const float* __restrict__ w3) {
    int e   = blockIdx.z;
    int cnt = g_counts[e];
    int m0  = blockIdx.y * BM;
    if (m0 >= cnt) return;
    int n0  = blockIdx.x * BN;

    __shared__ float As [BK][2 * BM + 4];   // duplicated: {a,a} per element
    __shared__ float B1s[BK][BN + 4];
    __shared__ float B3s[BK][BN + 4];

    int tid = threadIdx.x;
    int tx = tid & 15, ty = tid >> 4;

    // loader assignment: 64 rows x 4 float4 columns
    int la_m = tid >> 2;
    int la_k = (tid & 3) * 4;

    int ar     = m0 + la_m;
    int a_slot = g_slot[e * NT + min(ar, cnt - 1)];
    const float* xrow  = x  + (size_t)(a_slot >> 1) * DD;
    const float* w1row = w1 + ((size_t)e * HH + n0 + la_m) * DD;
    const float* w3row = w3 + ((size_t)e * HH + n0 + la_m) * DD;

    unsigned long long acc1[4][2] = {}, acc3[4][2] = {};

    for (int kt = 0; kt < DD; kt += BK) {
        float4 av = *(const float4*)(xrow  + kt + la_k);
        float4 b1 = *(const float4*)(w1row + kt + la_k);
        float4 b3 = *(const float4*)(w3row + kt + la_k);
        // duplicated-A stores (float2 {v,v})
        *(float2*)&As[la_k + 0][2 * la_m] = make_float2(av.x, av.x);
        *(float2*)&As[la_k + 1][2 * la_m] = make_float2(av.y, av.y);
        *(float2*)&As[la_k + 2][2 * la_m] = make_float2(av.z, av.z);
        *(float2*)&As[la_k + 3][2 * la_m] = make_float2(av.w, av.w);
        B1s[la_k + 0][la_m] = b1.x; B1s[la_k + 1][la_m] = b1.y;
        B1s[la_k + 2][la_m] = b1.z; B1s[la_k + 3][la_m] = b1.w;
        B3s[la_k + 0][la_m] = b3.x; B3s[la_k + 1][la_m] = b3.y;
        B3s[la_k + 2][la_m] = b3.z; B3s[la_k + 3][la_m] = b3.w;
        __syncthreads();
#pragma unroll
        for (int k = 0; k < BK; k++) {
            ulonglong2 aA = *(const ulonglong2*)&As[k][ty * 8];      // {a0,a0},{a1,a1}
            ulonglong2 aB = *(const ulonglong2*)&As[k][ty * 8 + 4];  // {a2,a2},{a3,a3}
            ulonglong2 p1 = *(const ulonglong2*)&B1s[k][tx * 4];     // {b0,b1},{b2,b3}
            ulonglong2 p3 = *(const ulonglong2*)&B3s[k][tx * 4];
            fma2(acc1[0][0], aA.x, p1.x); fma2(acc1[0][1], aA.x, p1.y);
            fma2(acc1[1][0], aA.y, p1.x); fma2(acc1[1][1], aA.y, p1.y);
            fma2(acc1[2][0], aB.x, p1.x); fma2(acc1[2][1], aB.x, p1.y);
            fma2(acc1[3][0], aB.y, p1.x); fma2(acc1[3][1], aB.y, p1.y);
            fma2(acc3[0][0], aA.x, p3.x); fma2(acc3[0][1], aA.x, p3.y);
            fma2(acc3[1][0], aA.y, p3.x); fma2(acc3[1][1], aA.y, p3.y);
            fma2(acc3[2][0], aB.x, p3.x); fma2(acc3[2][1], aB.x, p3.y);
            fma2(acc3[3][0], aB.y, p3.x); fma2(acc3[3][1], aB.y, p3.y);
        }
        __syncthreads();
    }

    // epilogue: h = silu(g1) * g3, write to hbuf[slot]
#pragma unroll
    for (int i = 0; i < 4; i++) {
        int r = m0 + ty * 4 + i;
        if (r >= cnt) continue;
        int slot = g_slot[e * NT + r];
        float2 u1a = unpack2(acc1[i][0]), u1b = unpack2(acc1[i][1]);
        float2 u3a = unpack2(acc3[i][0]), u3b = unpack2(acc3[i][1]);
        float h0, h1, h2, h3, z;
        z = u1a.x; h0 = (z / (1.f + expf(-z))) * u3a.x;
        z = u1a.y; h1 = (z / (1.f + expf(-z))) * u3a.y;
        z = u1b.x; h2 = (z / (1.f + expf(-z))) * u3b.x;
        z = u1b.y; h3 = (z / (1.f + expf(-z))) * u3b.y;
        *(float4*)(g_hbuf + (size_t)slot * HH + n0 + tx * 4) =
            make_float4(h0, h1, h2, h3);
    }
}

// ============================================================
// 3) grouped GEMM #2:  y = (h @ w2^T) * route_weight  -> ybuf[slot]
// ============================================================
__global__ __launch_bounds__(256) void ffn2_k(const float* __restrict__ w2) {
    int e   = blockIdx.z;
    int cnt = g_counts[e];
    int m0  = blockIdx.y * BM;
    if (m0 >= cnt) return;
    int n0  = blockIdx.x * BN;   // over D

    __shared__ float As[BK][2 * BM + 4];
    __shared__ float Bs[BK][BN + 4];

    int tid = threadIdx.x;
    int tx = tid & 15, ty = tid >> 4;
    int la_m = tid >> 2;
    int la_k = (tid & 3) * 4;

    int ar     = m0 + la_m;
    int a_slot = g_slot[e * NT + min(ar, cnt - 1)];
    const float* hrow  = g_hbuf + (size_t)a_slot * HH;
    const float* w2row = w2 + ((size_t)e * DD + n0 + la_m) * HH;

    unsigned long long acc[4][2] = {};

    for (int kt = 0; kt < HH; kt += BK) {
        float4 av = *(const float4*)(hrow  + kt + la_k);
        float4 bv = *(const float4*)(w2row + kt + la_k);
        *(float2*)&As[la_k + 0][2 * la_m] = make_float2(av.x, av.x);
        *(float2*)&As[la_k + 1][2 * la_m] = make_float2(av.y, av.y);
        *(float2*)&As[la_k + 2][2 * la_m] = make_float2(av.z, av.z);
        *(float2*)&As[la_k + 3][2 * la_m] = make_float2(av.w, av.w);
        Bs[la_k + 0][la_m] = bv.x; Bs[la_k + 1][la_m] = bv.y;
        Bs[la_k + 2][la_m] = bv.z; Bs[la_k + 3][la_m] = bv.w;
        __syncthreads();
#pragma unroll
        for (int k = 0; k < BK; k++) {
            ulonglong2 aA = *(const ulonglong2*)&As[k][ty * 8];
            ulonglong2 aB = *(const ulonglong2*)&As[k][ty * 8 + 4];
            ulonglong2 bp = *(const ulonglong2*)&Bs[k][tx * 4];
            fma2(acc[0][0], aA.x, bp.x); fma2(acc[0][1], aA.x, bp.y);
            fma2(acc[1][0], aA.y, bp.x); fma2(acc[1][1], aA.y, bp.y);
            fma2(acc[2][0], aB.x, bp.x); fma2(acc[2][1], aB.x, bp.y);
            fma2(acc[3][0], aB.y, bp.x); fma2(acc[3][1], aB.y, bp.y);
        }
        __syncthreads();
    }

#pragma unroll
    for (int i = 0; i < 4; i++) {
        int r = m0 + ty * 4 + i;
        if (r >= cnt) continue;
        int slot  = g_slot[e * NT + r];
        float wgt = g_rw[e * NT + r];
        float2 ua = unpack2(acc[i][0]), ub = unpack2(acc[i][1]);
        *(float4*)(g_ybuf + (size_t)slot * DD + n0 + tx * 4) =
            make_float4(wgt * ua.x, wgt * ua.y, wgt * ub.x, wgt * ub.y);
    }
}

// ============================================================
// 4) combine: out[n] = y[n,k=0] + y[n,k=1]  (deterministic, no atomics)
// ============================================================
__global__ void combine_k(float* __restrict__ out) {
    size_t f = (size_t)blockIdx.x * blockDim.x + threadIdx.x;   // float4 index
    size_t total = (size_t)NT * DD / 4;
    if (f >= total) return;
    size_t base = f * 4;
    size_t n = base / DD;
    size_t d = base % DD;
    const float4* y = (const float4*)g_ybuf;
    float4 a = y[((n * 2) * DD + d) >> 2];
    float4 b = y[((n * 2 + 1) * DD + d) >> 2];
    ((float4*)out)[f] = make_float4(a.x + b.x, a.y + b.y, a.z + b.z, a.w + b.w);
}

// ============================================================
extern "C" void kernel_launch(void* const* d_in, const int* in_sizes, int n_in,
                              void* d_out, int out_size) {
    const float* x  = (const float*)d_in[0];   // [8,4096,512]
    const float* gw = (const float*)d_in[1];   // [8,512]
    const float* w1 = (const float*)d_in[2];   // [8,1536,512]
    const float* w3 = (const float*)d_in[3];   // [8,1536,512]
    const float* w2 = (const float*)d_in[4];   // [8,512,1536]
    float* out = (float*)d_out;

    zero_counts_k<<<1, 32>>>();
    gate_k<<<NT / 8, 256>>>(x, gw);
    ffn1_k<<<dim3(HH / BN, NT / BM, NE), 256>>>(x, w1, w3);
    ffn2_k<<<dim3(DD / BN, NT / BM, NE), 256>>>(w2);
    combine_k<<<(NT * DD / 4 + 255) / 256, 256>>>(out);
}

// round 3
// speedup vs baseline: 2.7310x; 2.7310x over previous
#include <cuda_runtime.h>
#include <cuda_bf16.h>
#include <math.h>
#include <stdint.h>

#define NT 32768
#define DD 512
#define HH 1536
#define NE 8
#define NW (NE * HH * DD)

#define BM 128
#define BN 64
#define KC 32
#define RS 80              // smem row stride bytes (40 bf16) -> conflict-free ldmatrix

// ---------------- device scratch ----------------
__device__ int   g_counts[NE];
__device__ int   g_slot[NE * NT];
__device__ float g_rw[NE * NT];
__device__ __nv_bfloat16 g_xhi[(size_t)NE * NT * DD];
__device__ __nv_bfloat16 g_xlo[(size_t)NE * NT * DD];
__device__ __nv_bfloat16 g_hhi[(size_t)NE * NT * HH];
__device__ __nv_bfloat16 g_hlo[(size_t)NE * NT * HH];
__device__ float g_ybuf[(size_t)NT * 2 * DD];
__device__ __nv_bfloat16 g_w1hi[(size_t)NW], g_w1lo[(size_t)NW];
__device__ __nv_bfloat16 g_w3hi[(size_t)NW], g_w3lo[(size_t)NW];
__device__ __nv_bfloat16 g_w2hi[(size_t)NW], g_w2lo[(size_t)NW];

// ---------------- helpers ----------------
__device__ __forceinline__ uint32_t smem_u32(const void* p) {
    uint32_t a;
    asm("{ .reg .u64 t; cvta.to.shared.u64 t, %1; cvt.u32.u64 %0, t; }"
        : "=r"(a) : "l"(p));
    return a;
}
#define CPA(sm, gp) asm volatile("cp.async.cg.shared.global [%0], [%1], 16;" :: "r"(sm), "l"(gp) : "memory")
#define CPA_COMMIT() asm volatile("cp.async.commit_group;" ::: "memory")
#define CPA_WAIT1()  asm volatile("cp.async.wait_group 1;" ::: "memory")
#define CPA_WAIT0()  asm volatile("cp.async.wait_group 0;" ::: "memory")

__device__ __forceinline__ void ldsm4(uint32_t* r, uint32_t a) {
    asm volatile("ldmatrix.sync.aligned.m8n8.x4.shared.b16 {%0,%1,%2,%3}, [%4];"
                 : "=r"(r[0]), "=r"(r[1]), "=r"(r[2]), "=r"(r[3]) : "r"(a));
}
__device__ __forceinline__ void mma16816(float* d, const uint32_t* a, const uint32_t* b) {
    asm volatile("mma.sync.aligned.m16n8k16.row.col.f32.bf16.bf16.f32 "
                 "{%0,%1,%2,%3}, {%4,%5,%6,%7}, {%8,%9}, {%0,%1,%2,%3};"
                 : "+f"(d[0]), "+f"(d[1]), "+f"(d[2]), "+f"(d[3])
                 : "r"(a[0]), "r"(a[1]), "r"(a[2]), "r"(a[3]), "r"(b[0]), "r"(b[1]));
}
__device__ __forceinline__ uint32_t packbf(__nv_bfloat16 a, __nv_bfloat16 b) {
    return (uint32_t)__bfloat16_as_ushort(a) | ((uint32_t)__bfloat16_as_ushort(b) << 16);
}
__device__ __forceinline__ void split2(float v, __nv_bfloat16& h, __nv_bfloat16& l) {
    h = __float2bfloat16(v);
    l = __float2bfloat16(v - __bfloat162float(h));
}

// ============================================================
__global__ void zero_counts_k() {
    if (threadIdx.x < NE) g_counts[threadIdx.x] = 0;
}

__global__ void gate_k(const float* __restrict__ x, const float* __restrict__ gw) {
    __shared__ float sgw[NE * DD];
    for (int i = threadIdx.x; i < NE * DD; i += blockDim.x) sgw[i] = gw[i];
    __syncthreads();
    int warp = threadIdx.x >> 5, lane = threadIdx.x & 31;
    int n = blockIdx.x * (blockDim.x >> 5) + warp;
    if (n >= NT) return;
    const float* xr = x + (size_t)n * DD;
    float acc[NE];
#pragma unroll
    for (int e = 0; e < NE; e++) acc[e] = 0.f;
    for (int d = lane; d < DD; d += 32) {
        float xv = xr[d];
#pragma unroll
        for (int e = 0; e < NE; e++) acc[e] += xv * sgw[e * DD + d];
    }
#pragma unroll
    for (int e = 0; e < NE; e++)
#pragma unroll
        for (int off = 16; off > 0; off >>= 1)
            acc[e] += __shfl_down_sync(0xffffffffu, acc[e], off);
    if (lane == 0) {
        float b0 = -INFINITY, b1 = -INFINITY;
        int i0 = 0, i1 = 0;
#pragma unroll
        for (int e = 0; e < NE; e++) {
            float v = acc[e];
            if (v > b0) { b1 = b0; i1 = i0; b0 = v; i0 = e; }
            else if (v > b1) { b1 = v; i1 = e; }
        }
        float ex = expf(b1 - b0);
        float inv = 1.f / (1.f + ex);
        int p0 = atomicAdd(&g_counts[i0], 1);
        g_slot[i0 * NT + p0] = n * 2 + 0;
        g_rw[i0 * NT + p0]   = inv;
        int p1 = atomicAdd(&g_counts[i1], 1);
        g_slot[i1 * NT + p1] = n * 2 + 1;
        g_rw[i1 * NT + p1]   = ex * inv;
    }
}

__global__ void gather_x_k(const float* __restrict__ x) {
    int e = blockIdx.y, r = blockIdx.x;
    if (r >= g_counts[e]) return;
    int tok = g_slot[e * NT + r] >> 1;
    const float4* src = (const float4*)(x + (size_t)tok * DD);
    size_t dst = ((size_t)e * NT + r) * DD;
    int c = threadIdx.x;
    float4 v = src[c];
    __nv_bfloat16 h0, l0, h1, l1, h2, l2, h3, l3;
    split2(v.x, h0, l0); split2(v.y, h1, l1);
    split2(v.z, h2, l2); split2(v.w, h3, l3);
    ((uint2*)(g_xhi + dst))[c] = make_uint2(packbf(h0, h1), packbf(h2, h3));
    ((uint2*)(g_xlo + dst))[c] = make_uint2(packbf(l0, l1), packbf(l2, l3));
}

__global__ void convert_w_k(const float* __restrict__ w1,
                            const float* __restrict__ w3,
                            const float* __restrict__ w2) {
    size_t i = (size_t)blockIdx.x * blockDim.x + threadIdx.x;
    if (i >= NW / 4) return;
    __nv_bfloat16 h0, l0, h1, l1, h2, l2, h3, l3;
    float4 v;
    v = ((const float4*)w1)[i];
    split2(v.x, h0, l0); split2(v.y, h1, l1); split2(v.z, h2, l2); split2(v.w, h3, l3);
    ((uint2*)g_w1hi)[i] = make_uint2(packbf(h0, h1), packbf(h2, h3));
    ((uint2*)g_w1lo)[i] = make_uint2(packbf(l0, l1), packbf(l2, l3));
    v = ((const float4*)w3)[i];
    split2(v.x, h0, l0); split2(v.y, h1, l1); split2(v.z, h2, l2); split2(v.w, h3, l3);
    ((uint2*)g_w3hi)[i] = make_uint2(packbf(h0, h1), packbf(h2, h3));
    ((uint2*)g_w3lo)[i] = make_uint2(packbf(l0, l1), packbf(l2, l3));
    v = ((const float4*)w2)[i];
    split2(v.x, h0, l0); split2(v.y, h1, l1); split2(v.z, h2, l2); split2(v.w, h3, l3);
    ((uint2*)g_w2hi)[i] = make_uint2(packbf(h0, h1), packbf(h2, h3));
    ((uint2*)g_w2lo)[i] = make_uint2(packbf(l0, l1), packbf(l2, l3));
}

// ============================================================
// ffn1: g1 = X@w1^T, g3 = X@w3^T (3xBF16 via mma.sync), h = silu(g1)*g3
// smem stage: AH(10240) AL(10240) B1H B1L B3H B3L (5120 each) = 40960B x2
// ============================================================
#define F1_STG 40960
#define F1_AH  0
#define F1_AL  10240
#define F1_B1H 20480
#define F1_B1L 25600
#define F1_B3H 30720
#define F1_B3L 35840

__global__ __launch_bounds__(256, 1)
void ffn1_k() {
    int e = blockIdx.z;
    int cnt = g_counts[e];
    int m0 = blockIdx.y * BM;
    if (m0 >= cnt) return;
    int n0 = blockIdx.x * BN;

    extern __shared__ __align__(128) char smem[];
    uint32_t sb = smem_u32(smem);

    int tid = threadIdx.x, lane = tid & 31, wid = tid >> 5;
    int warp_m = wid & 3, warp_n = wid >> 2;

    size_t ebase = (size_t)e * NT;
    size_t wbase = (size_t)e * HH + n0;

    // loader indices
    int Lrow = tid >> 2, Lch = tid & 3;     // B rows / A rows
    int ArgA = min(m0 + Lrow, cnt - 1);
    int ArgA2 = min(m0 + Lrow + 64, cnt - 1);

#define F1_LOAD(STOFF, KCV) do {                                               \
        size_t sa1 = ((size_t)(ebase + ArgA)) * DD + (KCV) + Lch * 8;          \
        size_t sa2 = ((size_t)(ebase + ArgA2)) * DD + (KCV) + Lch * 8;         \
        uint32_t d1 = sb + (STOFF) + Lrow * RS + Lch * 16;                     \
        uint32_t d2 = d1 + 64 * RS;                                            \
        CPA(d1 + F1_AH, g_xhi + sa1); CPA(d1 + F1_AL, g_xlo + sa1);            \
        CPA(d2 + F1_AH, g_xhi + sa2); CPA(d2 + F1_AL, g_xlo + sa2);            \
        size_t sbf = ((size_t)(wbase + Lrow)) * DD + (KCV) + Lch * 8;          \
        CPA(d1 + F1_B1H, g_w1hi + sbf); CPA(d1 + F1_B1L, g_w1lo + sbf);        \
        CPA(d1 + F1_B3H, g_w3hi + sbf); CPA(d1 + F1_B3L, g_w3lo + sbf);        \
        CPA_COMMIT();                                                          \
    } while (0)

    // ldmatrix lane offsets
    uint32_t aoff = (uint32_t)(warp_m * 32 + (lane & 15)) * RS + (lane >> 4) * 16;
    uint32_t boff = (uint32_t)(warp_n * 32 + (lane & 7) + ((lane >> 4) ? 8 : 0)) * RS
                    + ((lane >> 3) & 1) * 16;

    float acc1[2][4][4], acc3[2][4][4];
#pragma unroll
    for (int a = 0; a < 2; a++)
#pragma unroll
        for (int b = 0; b < 4; b++)
#pragma unroll
            for (int c = 0; c < 4; c++) { acc1[a][b][c] = 0.f; acc3[a][b][c] = 0.f; }

    const int NIT = DD / KC;
    F1_LOAD(0, 0);
    for (int it = 0; it < NIT; it++) {
        uint32_t stg = (it & 1) ? F1_STG : 0;
        if (it + 1 < NIT) {
            uint32_t stg2 = ((it + 1) & 1) ? F1_STG : 0;
            F1_LOAD(stg2, (it + 1) * KC);
            CPA_WAIT1();
        } else {
            CPA_WAIT0();
        }
        __syncthreads();
#pragma unroll
        for (int ks = 0; ks < 2; ks++) {
            uint32_t kb = ks * 32;
            uint32_t ah[2][4], al[2][4];
            ldsm4(ah[0], sb + stg + F1_AH + aoff + kb);
            ldsm4(ah[1], sb + stg + F1_AH + aoff + 16 * RS + kb);
            ldsm4(al[0], sb + stg + F1_AL + aoff + kb);
            ldsm4(al[1], sb + stg + F1_AL + aoff + 16 * RS + kb);
            uint32_t b1h[2][4], b1l[2][4], b3h[2][4], b3l[2][4];
#pragma unroll
            for (int g = 0; g < 2; g++) {
                uint32_t bo = boff + g * 16 * RS + kb;
                ldsm4(b1h[g], sb + stg + F1_B1H + bo);
                ldsm4(b1l[g], sb + stg + F1_B1L + bo);
                ldsm4(b3h[g], sb + stg + F1_B3H + bo);
                ldsm4(b3l[g], sb + stg + F1_B3L + bo);
            }
#pragma unroll
            for (int mt = 0; mt < 2; mt++)
#pragma unroll
                for (int nt = 0; nt < 4; nt++) {
                    int g = nt >> 1, sl = (nt & 1) * 2;
                    mma16816(acc1[mt][nt], ah[mt], &b1h[g][sl]);
                    mma16816(acc1[mt][nt], ah[mt], &b1l[g][sl]);
                    mma16816(acc1[mt][nt], al[mt], &b1h[g][sl]);
                    mma16816(acc3[mt][nt], ah[mt], &b3h[g][sl]);
                    mma16816(acc3[mt][nt], ah[mt], &b3l[g][sl]);
                    mma16816(acc3[mt][nt], al[mt], &b3h[g][sl]);
                }
        }
        __syncthreads();
    }

    // epilogue: h = silu(g1)*g3 -> bf16 hi/lo
    int trow = lane >> 2, tc2 = (lane & 3) * 2;
#pragma unroll
    for (int mt = 0; mt < 2; mt++)
#pragma unroll
        for (int half = 0; half < 2; half++) {
            int rloc = warp_m * 32 + mt * 16 + trow + half * 8;
            int rg = m0 + rloc;
            if (rg >= cnt) continue;
            size_t hrow = (ebase + rg) * HH + n0 + warp_n * 32;
#pragma unroll
            for (int nt = 0; nt < 4; nt++) {
                float z0 = acc1[mt][nt][half * 2];
                float z1 = acc1[mt][nt][half * 2 + 1];
                float h0 = z0 / (1.f + __expf(-z0)) * acc3[mt][nt][half * 2];
                float h1 = z1 / (1.f + __expf(-z1)) * acc3[mt][nt][half * 2 + 1];
                __nv_bfloat16 a0, b0, a1, b1;
                split2(h0, a0, b0); split2(h1, a1, b1);
                *(uint32_t*)(g_hhi + hrow + nt * 8 + tc2) = packbf(a0, a1);
                *(uint32_t*)(g_hlo + hrow + nt * 8 + tc2) = packbf(b0, b1);
            }
        }
#undef F1_LOAD
}

// ============================================================
// ffn2: y = (h @ w2^T) * rw -> ybuf[slot]
// smem stage: AH(10240) AL(10240) BH(5120) BL(5120) = 30720B x2
// ============================================================
#define F2_STG 30720
#define F2_AH 0
#define F2_AL 10240
#define F2_BH 20480
#define F2_BL 25600

__global__ __launch_bounds__(256, 1)
void ffn2_k() {
    int e = blockIdx.z;
    int cnt = g_counts[e];
    int m0 = blockIdx.y * BM;
    if (m0 >= cnt) return;
    int n0 = blockIdx.x * BN;

    extern __shared__ __align__(128) char smem[];
    uint32_t sb = smem_u32(smem);

    int tid = threadIdx.x, lane = tid & 31, wid = tid >> 5;
    int warp_m = wid & 3, warp_n = wid >> 2;

    size_t ebase = (size_t)e * NT;
    size_t wbase = (size_t)e * DD + n0;

    int Lrow = tid >> 2, Lch = tid & 3;
    int ArgA = min(m0 + Lrow, cnt - 1);
    int ArgA2 = min(m0 + Lrow + 64, cnt - 1);

#define F2_LOAD(STOFF, KCV) do {                                               \
        size_t sa1 = ((size_t)(ebase + ArgA)) * HH + (KCV) + Lch * 8;          \
        size_t sa2 = ((size_t)(ebase + ArgA2)) * HH + (KCV) + Lch * 8;         \
        uint32_t d1 = sb + (STOFF) + Lrow * RS + Lch * 16;                     \
        uint32_t d2 = d1 + 64 * RS;                                            \
        CPA(d1 + F2_AH, g_hhi + sa1); CPA(d1 + F2_AL, g_hlo + sa1);            \
        CPA(d2 + F2_AH, g_hhi + sa2); CPA(d2 + F2_AL, g_hlo + sa2);            \
        size_t sbf = ((size_t)(wbase + Lrow)) * HH + (KCV) + Lch * 8;          \
        CPA(d1 + F2_BH, g_w2hi + sbf); CPA(d1 + F2_BL, g_w2lo + sbf);          \
        CPA_COMMIT();                                                          \
    } while (0)

    uint32_t aoff = (uint32_t)(warp_m * 32 + (lane & 15)) * RS + (lane >> 4) * 16;
    uint32_t boff = (uint32_t)(warp_n * 32 + (lane & 7) + ((lane >> 4) ? 8 : 0)) * RS
                    + ((lane >> 3) & 1) * 16;

    float acc[2][4][4];
#pragma unroll
    for (int a = 0; a < 2; a++)
#pragma unroll
        for (int b = 0; b < 4; b++)
#pragma unroll
            for (int c = 0; c < 4; c++) acc[a][b][c] = 0.f;

    const int NIT = HH / KC;
    F2_LOAD(0, 0);
    for (int it = 0; it < NIT; it++) {
        uint32_t stg = (it & 1) ? F2_STG : 0;
        if (it + 1 < NIT) {
            uint32_t stg2 = ((it + 1) & 1) ? F2_STG : 0;
            F2_LOAD(stg2, (it + 1) * KC);
            CPA_WAIT1();
        } else {
            CPA_WAIT0();
        }
        __syncthreads();
#pragma unroll
        for (int ks = 0; ks < 2; ks++) {
            uint32_t kb = ks * 32;
            uint32_t ah[2][4], al[2][4];
            ldsm4(ah[0], sb + stg + F2_AH + aoff + kb);
            ldsm4(ah[1], sb + stg + F2_AH + aoff + 16 * RS + kb);
            ldsm4(al[0], sb + stg + F2_AL + aoff + kb);
            ldsm4(al[1], sb + stg + F2_AL + aoff + 16 * RS + kb);
            uint32_t bh[2][4], bl[2][4];
#pragma unroll
            for (int g = 0; g < 2; g++) {
                uint32_t bo = boff + g * 16 * RS + kb;
                ldsm4(bh[g], sb + stg + F2_BH + bo);
                ldsm4(bl[g], sb + stg + F2_BL + bo);
            }
#pragma unroll
            for (int mt = 0; mt < 2; mt++)
#pragma unroll
                for (int nt = 0; nt < 4; nt++) {
                    int g = nt >> 1, sl = (nt & 1) * 2;
                    mma16816(acc[mt][nt], ah[mt], &bh[g][sl]);
                    mma16816(acc[mt][nt], ah[mt], &bl[g][sl]);
                    mma16816(acc[mt][nt], al[mt], &bh[g][sl]);
                }
        }
        __syncthreads();
    }

    int trow = lane >> 2, tc2 = (lane & 3) * 2;
#pragma unroll
    for (int mt = 0; mt < 2; mt++)
#pragma unroll
        for (int half = 0; half < 2; half++) {
            int rloc = warp_m * 32 + mt * 16 + trow + half * 8;
            int rg = m0 + rloc;
            if (rg >= cnt) continue;
            int slot = g_slot[e * NT + rg];
            float wgt = g_rw[e * NT + rg];
            float* yp = g_ybuf + (size_t)slot * DD + n0 + warp_n * 32;
#pragma unroll
            for (int nt = 0; nt < 4; nt++) {
                float v0 = acc[mt][nt][half * 2] * wgt;
                float v1 = acc[mt][nt][half * 2 + 1] * wgt;
                *(float2*)(yp + nt * 8 + tc2) = make_float2(v0, v1);
            }
        }
#undef F2_LOAD
}

// ============================================================
__global__ void combine_k(float* __restrict__ out) {
    size_t f = (size_t)blockIdx.x * blockDim.x + threadIdx.x;
    size_t total = (size_t)NT * DD / 4;
    if (f >= total) return;
    size_t base = f * 4;
    size_t n = base / DD, d = base % DD;
    const float4* y = (const float4*)g_ybuf;
    float4 a = y[((n * 2) * DD + d) >> 2];
    float4 b = y[((n * 2 + 1) * DD + d) >> 2];
    ((float4*)out)[f] = make_float4(a.x + b.x, a.y + b.y, a.z + b.z, a.w + b.w);
}

// ============================================================
extern "C" void kernel_launch(void* const* d_in, const int* in_sizes, int n_in,
                              void* d_out, int out_size) {
    const float* x  = (const float*)d_in[0];
    const float* gw = (const float*)d_in[1];
    const float* w1 = (const float*)d_in[2];
    const float* w3 = (const float*)d_in[3];
    const float* w2 = (const float*)d_in[4];
    float* out = (float*)d_out;

    cudaFuncSetAttribute(ffn1_k, cudaFuncAttributeMaxDynamicSharedMemorySize, 2 * F1_STG);
    cudaFuncSetAttribute(ffn2_k, cudaFuncAttributeMaxDynamicSharedMemorySize, 2 * F2_STG);

    zero_counts_k<<<1, 32>>>();
    gate_k<<<NT / 8, 256>>>(x, gw);
    gather_x_k<<<dim3(NT, NE), 128>>>(x);
    convert_w_k<<<(NW / 4 + 255) / 256, 256>>>(w1, w3, w2);
    ffn1_k<<<dim3(HH / BN, NT / BM, NE), 256, 2 * F1_STG>>>();
    ffn2_k<<<dim3(DD / BN, NT / BM, NE), 256, 2 * F2_STG>>>();
    combine_k<<<(NT * DD / 4 + 255) / 256, 256>>>(out);
}